// round 5
// baseline (speedup 1.0000x reference)
#include <cuda_runtime.h>

#define NN 50000
#define EE 800000
#define DD 128
#define HH 128
#define GG 256

typedef unsigned long long ull;

// Scratch (__device__ globals — no allocs allowed)
__device__ int   g_indeg[NN];
__device__ float g_dinv[NN];
__device__ int   g_row_off[NN + 1];
__device__ int   g_cursor[NN];
__device__ int   g_csr_src[EE];
__device__ float g_zws[(size_t)NN * HH];  // dinv[i] * (z @ W)[i]
__device__ float g_z1[(size_t)NN * HH];   // layer-1 output

#define SCAN_B 256
#define SCAN_NB ((NN + SCAN_B - 1) / SCAN_B)  // 196
__device__ int g_bsum[SCAN_NB];
__device__ int g_boff[SCAN_NB];

// f32x2 packed FMA (Blackwell FFMA2 — only reachable via PTX)
#define FFMA2(d, a, b) \
    asm("fma.rn.f32x2 %0, %1, %2, %0;" : "+l"(d) : "l"(a), "l"(b))

// ---------------------------------------------------------------------------
// Setup: degrees, scan, CSR
// ---------------------------------------------------------------------------
__global__ void k_indeg_zero() {
    int i = blockIdx.x * blockDim.x + threadIdx.x;
    if (i < NN) g_indeg[i] = 0;
}

__global__ void k_deg(const int* __restrict__ dst) {
    int e = blockIdx.x * blockDim.x + threadIdx.x;
    if (e < EE) atomicAdd(&g_indeg[dst[e]], 1);
}

__global__ void __launch_bounds__(SCAN_B) k_scan_block() {
    __shared__ int sh[SCAN_B];
    int i = blockIdx.x * SCAN_B + threadIdx.x;
    int v = (i < NN) ? g_indeg[i] : 0;
    sh[threadIdx.x] = v;
    __syncthreads();
    for (int off = SCAN_B / 2; off > 0; off >>= 1) {
        if (threadIdx.x < off) sh[threadIdx.x] += sh[threadIdx.x + off];
        __syncthreads();
    }
    if (threadIdx.x == 0) g_bsum[blockIdx.x] = sh[0];
}

__global__ void __launch_bounds__(SCAN_B) k_scan_top() {
    __shared__ int sh[SCAN_B];
    int t = threadIdx.x;
    int v = (t < SCAN_NB) ? g_bsum[t] : 0;
    sh[t] = v;
    __syncthreads();
    for (int off = 1; off < SCAN_B; off <<= 1) {
        int u = (t >= off) ? sh[t - off] : 0;
        __syncthreads();
        sh[t] += u;
        __syncthreads();
    }
    if (t < SCAN_NB) g_boff[t] = sh[t] - v;  // exclusive
    if (t == 0) g_row_off[NN] = EE;
}

// per-block scan fill + dinv (folded)
__global__ void __launch_bounds__(SCAN_B) k_scan_fill() {
    __shared__ int sh[SCAN_B];
    int i = blockIdx.x * SCAN_B + threadIdx.x;
    int t = threadIdx.x;
    int v = (i < NN) ? g_indeg[i] : 0;
    sh[t] = v;
    __syncthreads();
    for (int off = 1; off < SCAN_B; off <<= 1) {
        int u = (t >= off) ? sh[t - off] : 0;
        __syncthreads();
        sh[t] += u;
        __syncthreads();
    }
    if (i < NN) {
        int excl = g_boff[blockIdx.x] + sh[t] - v;
        g_row_off[i] = excl;
        g_cursor[i] = excl;
        g_dinv[i] = rsqrtf((float)v + 1.0f);  // +1 self-loop
    }
}

__global__ void k_fill(const int* __restrict__ src, const int* __restrict__ dst) {
    int e = blockIdx.x * blockDim.x + threadIdx.x;
    if (e < EE) {
        int p = atomicAdd(&g_cursor[dst[e]], 1);
        g_csr_src[p] = src[e];
    }
}

__global__ void k_zero_pool(float* __restrict__ out) {
    int i = blockIdx.x * blockDim.x + threadIdx.x;
    if (i < GG * 2 * HH) out[(size_t)NN * HH + i] = 0.0f;
}

// ---------------------------------------------------------------------------
// GEMM: g_zws = dinv[:,None] * (A @ W)  via packed f32x2 FFMA2.
// ---------------------------------------------------------------------------
#define GR 16
__global__ void __launch_bounds__(128) k_gemm(const float* __restrict__ A,
                                              const float* __restrict__ W) {
    __shared__ float2 xs2[GR][128];  // splatted: xs2[r][k] = {A[r][k], A[r][k]}
    const int row0 = blockIdx.x * GR;
    const int t = threadIdx.x;

    const float4* A4 = (const float4*)A;
    for (int i = t; i < GR * 32; i += 128) {
        int r = i >> 5, k4 = i & 31;
        float4 v = A4[(size_t)(row0 + r) * 32 + k4];
        xs2[r][4 * k4 + 0] = make_float2(v.x, v.x);
        xs2[r][4 * k4 + 1] = make_float2(v.y, v.y);
        xs2[r][4 * k4 + 2] = make_float2(v.z, v.z);
        xs2[r][4 * k4 + 3] = make_float2(v.w, v.w);
    }
    __syncthreads();

    const int cg = t & 31;
    const int rg = t >> 5;

    ull acc[4][2];
#pragma unroll
    for (int r = 0; r < 4; r++) { acc[r][0] = 0ULL; acc[r][1] = 0ULL; }

#pragma unroll 4
    for (int k = 0; k < 128; k++) {
        ulonglong2 wv = *(const ulonglong2*)&W[(size_t)k * 128 + 4 * cg];
#pragma unroll
        for (int r = 0; r < 4; r++) {
            ull a2 = *(const ull*)&xs2[4 * rg + r][k];
            FFMA2(acc[r][0], a2, wv.x);
            FFMA2(acc[r][1], a2, wv.y);
        }
    }

#pragma unroll
    for (int r = 0; r < 4; r++) {
        int row = row0 + 4 * rg + r;
        float di = g_dinv[row];
        float2 p0, p1;
        *(ull*)&p0 = acc[r][0];
        *(ull*)&p1 = acc[r][1];
        float4 o;
        o.x = di * p0.x; o.y = di * p0.y;
        o.z = di * p1.x; o.w = di * p1.y;
        ((float4*)g_zws)[(size_t)row * 32 + cg] = o;
    }
}

// ---------------------------------------------------------------------------
// Gather + epilogue: one warp per dst node, MLP-4 inner loop,
// 256-thread blocks (8 warps) for latency hiding.
// ---------------------------------------------------------------------------
__global__ void __launch_bounds__(256) k_gather(const float* __restrict__ b,
                                                const float* __restrict__ alpha,
                                                const int* __restrict__ batch,
                                                float* __restrict__ zout,
                                                float* __restrict__ pool,
                                                int pool_off) {
    int d = blockIdx.x * 8 + (threadIdx.x >> 5);
    if (d >= NN) return;
    int lane = threadIdx.x & 31;

    const float4* zws4 = (const float4*)g_zws;
    const int* __restrict__ csr = g_csr_src;
    int beg = g_row_off[d];
    int end = g_row_off[d + 1];

    float4 a0 = __ldg(&zws4[(size_t)d * 32 + lane]);  // self-loop term
    float4 a1 = make_float4(0.f, 0.f, 0.f, 0.f);
    float4 a2 = make_float4(0.f, 0.f, 0.f, 0.f);
    float4 a3 = make_float4(0.f, 0.f, 0.f, 0.f);

    int e = beg;
    // MLP-4 main loop: 4 independent index loads then 4 independent gathers
    for (; e + 3 < end; e += 4) {
        int s0 = __ldg(&csr[e + 0]);
        int s1 = __ldg(&csr[e + 1]);
        int s2 = __ldg(&csr[e + 2]);
        int s3 = __ldg(&csr[e + 3]);
        float4 v0 = __ldg(&zws4[(size_t)s0 * 32 + lane]);
        float4 v1 = __ldg(&zws4[(size_t)s1 * 32 + lane]);
        float4 v2 = __ldg(&zws4[(size_t)s2 * 32 + lane]);
        float4 v3 = __ldg(&zws4[(size_t)s3 * 32 + lane]);
        a0.x += v0.x; a0.y += v0.y; a0.z += v0.z; a0.w += v0.w;
        a1.x += v1.x; a1.y += v1.y; a1.z += v1.z; a1.w += v1.w;
        a2.x += v2.x; a2.y += v2.y; a2.z += v2.z; a2.w += v2.w;
        a3.x += v3.x; a3.y += v3.y; a3.z += v3.z; a3.w += v3.w;
    }
    for (; e < end; e++) {
        int s0 = __ldg(&csr[e]);
        float4 v0 = __ldg(&zws4[(size_t)s0 * 32 + lane]);
        a0.x += v0.x; a0.y += v0.y; a0.z += v0.z; a0.w += v0.w;
    }
    a0.x += a1.x + a2.x + a3.x;
    a0.y += a1.y + a2.y + a3.y;
    a0.z += a1.z + a2.z + a3.z;
    a0.w += a1.w + a2.w + a3.w;

    float di = g_dinv[d];
    float4 bb = __ldg(&((const float4*)b)[lane]);
    float4 al = __ldg(&((const float4*)alpha)[lane]);
    float4 h;
    h.x = di * a0.x + bb.x; h.x = (h.x > 0.f) ? h.x : al.x * h.x;
    h.y = di * a0.y + bb.y; h.y = (h.y > 0.f) ? h.y : al.y * h.y;
    h.z = di * a0.z + bb.z; h.z = (h.z > 0.f) ? h.z : al.z * h.z;
    h.w = di * a0.w + bb.w; h.w = (h.w > 0.f) ? h.w : al.w * h.w;

    ((float4*)zout)[(size_t)d * 32 + lane] = h;

    float* p = &pool[(size_t)batch[d] * (2 * HH) + pool_off + lane * 4];
    atomicAdd(p + 0, h.x);
    atomicAdd(p + 1, h.y);
    atomicAdd(p + 2, h.z);
    atomicAdd(p + 3, h.w);
}

// ---------------------------------------------------------------------------
extern "C" void kernel_launch(void* const* d_in, const int* in_sizes, int n_in,
                              void* d_out, int out_size) {
    const float* x     = (const float*)d_in[0];
    const int*   eidx  = (const int*)d_in[1];
    const int*   batch = (const int*)d_in[2];
    const float* W1    = (const float*)d_in[3];
    const float* b1    = (const float*)d_in[4];
    const float* W2    = (const float*)d_in[5];
    const float* b2    = (const float*)d_in[6];
    const float* alpha = (const float*)d_in[7];

    const int* src = eidx;       // edge_index[0]
    const int* dst = eidx + EE;  // edge_index[1]

    float* out  = (float*)d_out;
    float* pool = out + (size_t)NN * HH;

    // Setup (structure reused by both layers)
    k_indeg_zero<<<(NN + 255) / 256, 256>>>();
    k_deg<<<(EE + 255) / 256, 256>>>(dst);
    k_scan_block<<<SCAN_NB, SCAN_B>>>();
    k_scan_top<<<1, SCAN_B>>>();
    k_scan_fill<<<SCAN_NB, SCAN_B>>>();
    k_fill<<<(EE + 255) / 256, 256>>>(src, dst);
    k_zero_pool<<<(GG * 2 * HH + 255) / 256, 256>>>(out);

    float* z1;
    cudaGetSymbolAddress((void**)&z1, g_z1);

    // Layer 1
    k_gemm<<<NN / GR + (NN % GR ? 1 : 0), 128>>>(x, W1);
    k_gather<<<(NN + 7) / 8, 256>>>(b1, alpha, batch, z1, pool, 0);

    // Layer 2
    k_gemm<<<NN / GR + (NN % GR ? 1 : 0), 128>>>(z1, W2);
    k_gather<<<(NN + 7) / 8, 256>>>(b2, alpha, batch, out, pool, HH);
}

// round 9
// speedup vs baseline: 1.1123x; 1.1123x over previous
#include <cuda_runtime.h>

#define NN 50000
#define EE 800000
#define DD 128
#define HH 128
#define GG 256

typedef unsigned long long ull;

// Scratch (__device__ globals — no allocs allowed)
__device__ int   g_indeg[NN];
__device__ float g_dinv[NN];
__device__ int   g_row_off[NN + 1];
__device__ int   g_cursor[NN];
__device__ int   g_csr_src[EE];
__device__ float g_zws[(size_t)NN * HH];  // dinv[i] * (z @ W)[i]
__device__ float g_z1[(size_t)NN * HH];   // layer-1 output

#define SCAN_B 256
#define SCAN_NB ((NN + SCAN_B - 1) / SCAN_B)  // 196
#define POOL_ZB 64                             // 64 blocks x 256 thr x float4 = 65536 floats
__device__ int g_bsum[SCAN_NB];

// f32x2 packed FMA (Blackwell FFMA2 — only reachable via PTX)
#define FFMA2(d, a, b) \
    asm("fma.rn.f32x2 %0, %1, %2, %0;" : "+l"(d) : "l"(a), "l"(b))

// ---------------------------------------------------------------------------
// Setup
// ---------------------------------------------------------------------------
__global__ void k_indeg_zero() {
    int i = blockIdx.x * blockDim.x + threadIdx.x;
    if (i < NN) g_indeg[i] = 0;
}

__global__ void k_deg(const int* __restrict__ dst) {
    int e = blockIdx.x * blockDim.x + threadIdx.x;
    if (e < EE) atomicAdd(&g_indeg[dst[e]], 1);
}

// Block sums of indeg; extra blocks zero the pool region of d_out.
__global__ void __launch_bounds__(SCAN_B) k_scan_block(float* __restrict__ out) {
    if (blockIdx.x >= SCAN_NB) {
        int idx = (blockIdx.x - SCAN_NB) * SCAN_B + threadIdx.x;  // float4 index
        ((float4*)(out + (size_t)NN * HH))[idx] = make_float4(0.f, 0.f, 0.f, 0.f);
        return;
    }
    __shared__ int sh[SCAN_B];
    int i = blockIdx.x * SCAN_B + threadIdx.x;
    int v = (i < NN) ? g_indeg[i] : 0;
    sh[threadIdx.x] = v;
    __syncthreads();
    for (int off = SCAN_B / 2; off > 0; off >>= 1) {
        if (threadIdx.x < off) sh[threadIdx.x] += sh[threadIdx.x + off];
        __syncthreads();
    }
    if (threadIdx.x == 0) g_bsum[blockIdx.x] = sh[0];
}

// Fused: per-block offset (reduce bsum[0..bid)) + in-block exclusive scan
// + row_off/cursor/dinv writes. Deletes the serial top-scan kernel.
__global__ void __launch_bounds__(SCAN_B) k_scan_fill() {
    __shared__ int red[SCAN_B];
    __shared__ int sh[SCAN_B];
    const int bid = blockIdx.x;
    const int t = threadIdx.x;

    // block offset = sum of bsum[0..bid)
    red[t] = (t < bid) ? g_bsum[t] : 0;   // bid <= 195 < 256
    __syncthreads();
    for (int off = SCAN_B / 2; off > 0; off >>= 1) {
        if (t < off) red[t] += red[t + off];
        __syncthreads();
    }
    const int boff = red[0];

    int i = bid * SCAN_B + t;
    int v = (i < NN) ? g_indeg[i] : 0;
    sh[t] = v;
    __syncthreads();
    for (int off = 1; off < SCAN_B; off <<= 1) {
        int u = (t >= off) ? sh[t - off] : 0;
        __syncthreads();
        sh[t] += u;
        __syncthreads();
    }
    if (i < NN) {
        int excl = boff + sh[t] - v;
        g_row_off[i] = excl;
        g_cursor[i] = excl;
        g_dinv[i] = rsqrtf((float)v + 1.0f);  // +1 self-loop
    }
    if (bid == 0 && t == 0) g_row_off[NN] = EE;
}

__global__ void k_fill(const int* __restrict__ src, const int* __restrict__ dst) {
    int e = blockIdx.x * blockDim.x + threadIdx.x;
    if (e < EE) {
        int p = atomicAdd(&g_cursor[dst[e]], 1);
        g_csr_src[p] = src[e];
    }
}

// ---------------------------------------------------------------------------
// GEMM: g_zws = dinv[:,None] * (A @ W)  via packed f32x2 FFMA2. (R3-proven)
// ---------------------------------------------------------------------------
#define GR 16
__global__ void __launch_bounds__(128) k_gemm(const float* __restrict__ A,
                                              const float* __restrict__ W) {
    __shared__ float2 xs2[GR][128];  // splatted: xs2[r][k] = {A[r][k], A[r][k]}
    const int row0 = blockIdx.x * GR;
    const int t = threadIdx.x;

    const float4* A4 = (const float4*)A;
    for (int i = t; i < GR * 32; i += 128) {
        int r = i >> 5, k4 = i & 31;
        float4 v = A4[(size_t)(row0 + r) * 32 + k4];
        xs2[r][4 * k4 + 0] = make_float2(v.x, v.x);
        xs2[r][4 * k4 + 1] = make_float2(v.y, v.y);
        xs2[r][4 * k4 + 2] = make_float2(v.z, v.z);
        xs2[r][4 * k4 + 3] = make_float2(v.w, v.w);
    }
    __syncthreads();

    const int cg = t & 31;
    const int rg = t >> 5;

    ull acc[4][2];
#pragma unroll
    for (int r = 0; r < 4; r++) { acc[r][0] = 0ULL; acc[r][1] = 0ULL; }

#pragma unroll 4
    for (int k = 0; k < 128; k++) {
        ulonglong2 wv = *(const ulonglong2*)&W[(size_t)k * 128 + 4 * cg];
#pragma unroll
        for (int r = 0; r < 4; r++) {
            ull a2 = *(const ull*)&xs2[4 * rg + r][k];
            FFMA2(acc[r][0], a2, wv.x);
            FFMA2(acc[r][1], a2, wv.y);
        }
    }

#pragma unroll
    for (int r = 0; r < 4; r++) {
        int row = row0 + 4 * rg + r;
        float di = g_dinv[row];
        float2 p0, p1;
        *(ull*)&p0 = acc[r][0];
        *(ull*)&p1 = acc[r][1];
        float4 o;
        o.x = di * p0.x; o.y = di * p0.y;
        o.z = di * p1.x; o.w = di * p1.y;
        ((float4*)g_zws)[(size_t)row * 32 + cg] = o;
    }
}

// ---------------------------------------------------------------------------
// Gather + epilogue: one warp per dst node, MLP-2, 128-thread blocks.
// (exact R3-winning configuration — gather is L2-BW-bound, don't over-MLP)
// ---------------------------------------------------------------------------
__global__ void __launch_bounds__(128) k_gather(const float* __restrict__ b,
                                                const float* __restrict__ alpha,
                                                const int* __restrict__ batch,
                                                float* __restrict__ zout,
                                                float* __restrict__ pool,
                                                int pool_off) {
    int d = blockIdx.x * 4 + (threadIdx.x >> 5);
    if (d >= NN) return;
    int lane = threadIdx.x & 31;

    const float4* zws4 = (const float4*)g_zws;
    int beg = g_row_off[d];
    int end = g_row_off[d + 1];

    float4 acc = __ldg(&zws4[(size_t)d * 32 + lane]);  // self-loop term
    float4 acc2 = make_float4(0.f, 0.f, 0.f, 0.f);

    int e = beg;
    for (; e + 1 < end; e += 2) {
        int s0 = g_csr_src[e];
        int s1 = g_csr_src[e + 1];
        float4 v0 = __ldg(&zws4[(size_t)s0 * 32 + lane]);
        float4 v1 = __ldg(&zws4[(size_t)s1 * 32 + lane]);
        acc.x += v0.x; acc.y += v0.y; acc.z += v0.z; acc.w += v0.w;
        acc2.x += v1.x; acc2.y += v1.y; acc2.z += v1.z; acc2.w += v1.w;
    }
    if (e < end) {
        int s0 = g_csr_src[e];
        float4 v0 = __ldg(&zws4[(size_t)s0 * 32 + lane]);
        acc.x += v0.x; acc.y += v0.y; acc.z += v0.z; acc.w += v0.w;
    }
    acc.x += acc2.x; acc.y += acc2.y; acc.z += acc2.z; acc.w += acc2.w;

    float di = g_dinv[d];
    float4 bb = __ldg(&((const float4*)b)[lane]);
    float4 al = __ldg(&((const float4*)alpha)[lane]);
    float4 h;
    h.x = di * acc.x + bb.x; h.x = (h.x > 0.f) ? h.x : al.x * h.x;
    h.y = di * acc.y + bb.y; h.y = (h.y > 0.f) ? h.y : al.y * h.y;
    h.z = di * acc.z + bb.z; h.z = (h.z > 0.f) ? h.z : al.z * h.z;
    h.w = di * acc.w + bb.w; h.w = (h.w > 0.f) ? h.w : al.w * h.w;

    ((float4*)zout)[(size_t)d * 32 + lane] = h;

    float* p = &pool[(size_t)batch[d] * (2 * HH) + pool_off + lane * 4];
    atomicAdd(p + 0, h.x);
    atomicAdd(p + 1, h.y);
    atomicAdd(p + 2, h.z);
    atomicAdd(p + 3, h.w);
}

// ---------------------------------------------------------------------------
extern "C" void kernel_launch(void* const* d_in, const int* in_sizes, int n_in,
                              void* d_out, int out_size) {
    const float* x     = (const float*)d_in[0];
    const int*   eidx  = (const int*)d_in[1];
    const int*   batch = (const int*)d_in[2];
    const float* W1    = (const float*)d_in[3];
    const float* b1    = (const float*)d_in[4];
    const float* W2    = (const float*)d_in[5];
    const float* b2    = (const float*)d_in[6];
    const float* alpha = (const float*)d_in[7];

    const int* src = eidx;       // edge_index[0]
    const int* dst = eidx + EE;  // edge_index[1]

    float* out  = (float*)d_out;
    float* pool = out + (size_t)NN * HH;

    // Setup: 5 launches (was 7)
    k_indeg_zero<<<(NN + 255) / 256, 256>>>();
    k_deg<<<(EE + 255) / 256, 256>>>(dst);
    k_scan_block<<<SCAN_NB + POOL_ZB, SCAN_B>>>(out);
    k_scan_fill<<<SCAN_NB, SCAN_B>>>();
    k_fill<<<(EE + 255) / 256, 256>>>(src, dst);

    float* z1;
    cudaGetSymbolAddress((void**)&z1, g_z1);

    // Layer 1
    k_gemm<<<NN / GR + (NN % GR ? 1 : 0), 128>>>(x, W1);
    k_gather<<<(NN + 3) / 4, 128>>>(b1, alpha, batch, z1, pool, 0);

    // Layer 2
    k_gemm<<<NN / GR + (NN % GR ? 1 : 0), 128>>>(z1, W2);
    k_gather<<<(NN + 3) / 4, 128>>>(b2, alpha, batch, out, pool, HH);
}

// round 11
// speedup vs baseline: 1.1826x; 1.0632x over previous
#include <cuda_runtime.h>
#include <cuda_fp16.h>

#define NN 50000
#define EE 800000
#define DD 128
#define HH 128
#define GG 256

typedef unsigned long long ull;

// Scratch (__device__ globals — no allocs allowed)
__device__ int    g_indeg[NN];
__device__ float  g_dinv[NN];
__device__ int    g_row_off[NN + 1];
__device__ int    g_cursor[NN];
__device__ int    g_csr_src[EE];
__device__ __half g_zws[(size_t)NN * HH];  // fp16: dinv[i] * (z @ W)[i]
__device__ float  g_z1[(size_t)NN * HH];   // layer-1 output (fp32)

#define SCAN_B 256
#define SCAN_NB ((NN + SCAN_B - 1) / SCAN_B)  // 196
#define POOL_ZB 64                             // 64 blocks x 256 thr x float4 = 65536 floats
__device__ int g_bsum[SCAN_NB];

// f32x2 packed FMA (Blackwell FFMA2 — only reachable via PTX)
#define FFMA2(d, a, b) \
    asm("fma.rn.f32x2 %0, %1, %2, %0;" : "+l"(d) : "l"(a), "l"(b))

// ---------------------------------------------------------------------------
// Setup
// ---------------------------------------------------------------------------
__global__ void k_indeg_zero() {
    int i = blockIdx.x * blockDim.x + threadIdx.x;
    if (i < NN) g_indeg[i] = 0;
}

__global__ void k_deg(const int* __restrict__ dst) {
    int e = blockIdx.x * blockDim.x + threadIdx.x;
    if (e < EE) atomicAdd(&g_indeg[dst[e]], 1);
}

// Block sums of indeg; extra blocks zero the pool region of d_out.
__global__ void __launch_bounds__(SCAN_B) k_scan_block(float* __restrict__ out) {
    if (blockIdx.x >= SCAN_NB) {
        int idx = (blockIdx.x - SCAN_NB) * SCAN_B + threadIdx.x;  // float4 index
        ((float4*)(out + (size_t)NN * HH))[idx] = make_float4(0.f, 0.f, 0.f, 0.f);
        return;
    }
    __shared__ int sh[SCAN_B];
    int i = blockIdx.x * SCAN_B + threadIdx.x;
    int v = (i < NN) ? g_indeg[i] : 0;
    sh[threadIdx.x] = v;
    __syncthreads();
    for (int off = SCAN_B / 2; off > 0; off >>= 1) {
        if (threadIdx.x < off) sh[threadIdx.x] += sh[threadIdx.x + off];
        __syncthreads();
    }
    if (threadIdx.x == 0) g_bsum[blockIdx.x] = sh[0];
}

// Fused: per-block offset (reduce bsum[0..bid)) + in-block exclusive scan
// + row_off/cursor/dinv writes.
__global__ void __launch_bounds__(SCAN_B) k_scan_fill() {
    __shared__ int red[SCAN_B];
    __shared__ int sh[SCAN_B];
    const int bid = blockIdx.x;
    const int t = threadIdx.x;

    red[t] = (t < bid) ? g_bsum[t] : 0;   // bid <= 195 < 256
    __syncthreads();
    for (int off = SCAN_B / 2; off > 0; off >>= 1) {
        if (t < off) red[t] += red[t + off];
        __syncthreads();
    }
    const int boff = red[0];

    int i = bid * SCAN_B + t;
    int v = (i < NN) ? g_indeg[i] : 0;
    sh[t] = v;
    __syncthreads();
    for (int off = 1; off < SCAN_B; off <<= 1) {
        int u = (t >= off) ? sh[t - off] : 0;
        __syncthreads();
        sh[t] += u;
        __syncthreads();
    }
    if (i < NN) {
        int excl = boff + sh[t] - v;
        g_row_off[i] = excl;
        g_cursor[i] = excl;
        g_dinv[i] = rsqrtf((float)v + 1.0f);  // +1 self-loop
    }
    if (bid == 0 && t == 0) g_row_off[NN] = EE;
}

__global__ void k_fill(const int* __restrict__ src, const int* __restrict__ dst) {
    int e = blockIdx.x * blockDim.x + threadIdx.x;
    if (e < EE) {
        int p = atomicAdd(&g_cursor[dst[e]], 1);
        g_csr_src[p] = src[e];
    }
}

// ---------------------------------------------------------------------------
// GEMM: g_zws(fp16) = dinv[:,None] * (A @ W)  via packed f32x2 FFMA2.
// ---------------------------------------------------------------------------
#define GR 16
__global__ void __launch_bounds__(128) k_gemm(const float* __restrict__ A,
                                              const float* __restrict__ W) {
    __shared__ float2 xs2[GR][128];  // splatted: xs2[r][k] = {A[r][k], A[r][k]}
    const int row0 = blockIdx.x * GR;
    const int t = threadIdx.x;

    const float4* A4 = (const float4*)A;
    for (int i = t; i < GR * 32; i += 128) {
        int r = i >> 5, k4 = i & 31;
        float4 v = A4[(size_t)(row0 + r) * 32 + k4];
        xs2[r][4 * k4 + 0] = make_float2(v.x, v.x);
        xs2[r][4 * k4 + 1] = make_float2(v.y, v.y);
        xs2[r][4 * k4 + 2] = make_float2(v.z, v.z);
        xs2[r][4 * k4 + 3] = make_float2(v.w, v.w);
    }
    __syncthreads();

    const int cg = t & 31;
    const int rg = t >> 5;

    ull acc[4][2];
#pragma unroll
    for (int r = 0; r < 4; r++) { acc[r][0] = 0ULL; acc[r][1] = 0ULL; }

#pragma unroll 4
    for (int k = 0; k < 128; k++) {
        ulonglong2 wv = *(const ulonglong2*)&W[(size_t)k * 128 + 4 * cg];
#pragma unroll
        for (int r = 0; r < 4; r++) {
            ull a2 = *(const ull*)&xs2[4 * rg + r][k];
            FFMA2(acc[r][0], a2, wv.x);
            FFMA2(acc[r][1], a2, wv.y);
        }
    }

#pragma unroll
    for (int r = 0; r < 4; r++) {
        int row = row0 + 4 * rg + r;
        float di = g_dinv[row];
        float2 p0, p1;
        *(ull*)&p0 = acc[r][0];
        *(ull*)&p1 = acc[r][1];
        __half2 h0 = __floats2half2_rn(di * p0.x, di * p0.y);
        __half2 h1 = __floats2half2_rn(di * p1.x, di * p1.y);
        uint2 o;
        o.x = *(unsigned int*)&h0;
        o.y = *(unsigned int*)&h1;
        ((uint2*)g_zws)[(size_t)row * 32 + cg] = o;  // 256 B/row, coalesced
    }
}

// ---------------------------------------------------------------------------
// Gather + epilogue: one warp per dst node, MLP-2, 128-thread blocks.
// fp16 gather stream (LDG.64/lane), fp32 accumulation.
// ---------------------------------------------------------------------------
__device__ __forceinline__ void acc_h4(float4& a, uint2 u) {
    float2 f0 = __half22float2(*(__half2*)&u.x);
    float2 f1 = __half22float2(*(__half2*)&u.y);
    a.x += f0.x; a.y += f0.y; a.z += f1.x; a.w += f1.y;
}

__global__ void __launch_bounds__(128) k_gather(const float* __restrict__ b,
                                                const float* __restrict__ alpha,
                                                const int* __restrict__ batch,
                                                float* __restrict__ zout,
                                                float* __restrict__ pool,
                                                int pool_off) {
    int d = blockIdx.x * 4 + (threadIdx.x >> 5);
    if (d >= NN) return;
    int lane = threadIdx.x & 31;

    const uint2* zz = (const uint2*)g_zws;
    int beg = g_row_off[d];
    int end = g_row_off[d + 1];

    float4 acc = make_float4(0.f, 0.f, 0.f, 0.f);
    float4 acc2 = make_float4(0.f, 0.f, 0.f, 0.f);
    acc_h4(acc, __ldg(&zz[(size_t)d * 32 + lane]));  // self-loop term

    int e = beg;
    for (; e + 1 < end; e += 2) {
        int s0 = g_csr_src[e];
        int s1 = g_csr_src[e + 1];
        uint2 v0 = __ldg(&zz[(size_t)s0 * 32 + lane]);
        uint2 v1 = __ldg(&zz[(size_t)s1 * 32 + lane]);
        acc_h4(acc, v0);
        acc_h4(acc2, v1);
    }
    if (e < end) {
        int s0 = g_csr_src[e];
        acc_h4(acc, __ldg(&zz[(size_t)s0 * 32 + lane]));
    }
    acc.x += acc2.x; acc.y += acc2.y; acc.z += acc2.z; acc.w += acc2.w;

    float di = g_dinv[d];
    float4 bb = __ldg(&((const float4*)b)[lane]);
    float4 al = __ldg(&((const float4*)alpha)[lane]);
    float4 h;
    h.x = di * acc.x + bb.x; h.x = (h.x > 0.f) ? h.x : al.x * h.x;
    h.y = di * acc.y + bb.y; h.y = (h.y > 0.f) ? h.y : al.y * h.y;
    h.z = di * acc.z + bb.z; h.z = (h.z > 0.f) ? h.z : al.z * h.z;
    h.w = di * acc.w + bb.w; h.w = (h.w > 0.f) ? h.w : al.w * h.w;

    ((float4*)zout)[(size_t)d * 32 + lane] = h;

    float* p = &pool[(size_t)batch[d] * (2 * HH) + pool_off + lane * 4];
    atomicAdd(p + 0, h.x);
    atomicAdd(p + 1, h.y);
    atomicAdd(p + 2, h.z);
    atomicAdd(p + 3, h.w);
}

// ---------------------------------------------------------------------------
extern "C" void kernel_launch(void* const* d_in, const int* in_sizes, int n_in,
                              void* d_out, int out_size) {
    const float* x     = (const float*)d_in[0];
    const int*   eidx  = (const int*)d_in[1];
    const int*   batch = (const int*)d_in[2];
    const float* W1    = (const float*)d_in[3];
    const float* b1    = (const float*)d_in[4];
    const float* W2    = (const float*)d_in[5];
    const float* b2    = (const float*)d_in[6];
    const float* alpha = (const float*)d_in[7];

    const int* src = eidx;       // edge_index[0]
    const int* dst = eidx + EE;  // edge_index[1]

    float* out  = (float*)d_out;
    float* pool = out + (size_t)NN * HH;

    // Setup: 5 launches
    k_indeg_zero<<<(NN + 255) / 256, 256>>>();
    k_deg<<<(EE + 255) / 256, 256>>>(dst);
    k_scan_block<<<SCAN_NB + POOL_ZB, SCAN_B>>>(out);
    k_scan_fill<<<SCAN_NB, SCAN_B>>>();
    k_fill<<<(EE + 255) / 256, 256>>>(src, dst);

    float* z1;
    cudaGetSymbolAddress((void**)&z1, g_z1);

    // Layer 1
    k_gemm<<<NN / GR + (NN % GR ? 1 : 0), 128>>>(x, W1);
    k_gather<<<(NN + 3) / 4, 128>>>(b1, alpha, batch, z1, pool, 0);

    // Layer 2
    k_gemm<<<NN / GR + (NN % GR ? 1 : 0), 128>>>(z1, W2);
    k_gather<<<(NN + 3) / 4, 128>>>(b2, alpha, batch, out, pool, HH);
}

// round 12
// speedup vs baseline: 1.2473x; 1.0547x over previous
#include <cuda_runtime.h>
#include <cuda_fp16.h>

#define NN 50000
#define EE 800000
#define DD 128
#define HH 128
#define GG 256

typedef unsigned long long ull;

// Scratch (__device__ globals — no allocs allowed)
__device__ int    g_indeg[NN];
__device__ float  g_dinv[NN];
__device__ int    g_row_off[NN + 1];
__device__ int    g_cursor[NN];
__device__ int    g_csr_src[EE];
__device__ __half g_zws[(size_t)NN * HH];  // fp16: dinv[i] * (z @ W)[i]
__device__ float  g_z1[(size_t)NN * HH];   // layer-1 output (fp32)
__device__ int    g_gstart[GG + 1];        // per-graph node range (batch is sorted)

#define SCAN_B 256
#define SCAN_NB ((NN + SCAN_B - 1) / SCAN_B)  // 196
__device__ int g_bsum[SCAN_NB];

// f32x2 packed FMA (Blackwell FFMA2 — only reachable via PTX)
#define FFMA2(d, a, b) \
    asm("fma.rn.f32x2 %0, %1, %2, %0;" : "+l"(d) : "l"(a), "l"(b))

// ---------------------------------------------------------------------------
// Setup
// ---------------------------------------------------------------------------
__global__ void k_indeg_zero() {
    int i = blockIdx.x * blockDim.x + threadIdx.x;
    if (i < NN) g_indeg[i] = 0;
}

__global__ void k_deg(const int* __restrict__ dst) {
    int e = blockIdx.x * blockDim.x + threadIdx.x;
    if (e < EE) atomicAdd(&g_indeg[dst[e]], 1);
}

// Per-graph segment starts via binary search (batch is sorted ascending).
__global__ void k_gstart(const int* __restrict__ batch) {
    int g = threadIdx.x;  // 0..255
    int lo = 0, hi = NN;
    while (lo < hi) {
        int m = (lo + hi) >> 1;
        if (batch[m] < g) lo = m + 1; else hi = m;
    }
    g_gstart[g] = lo;
    if (g == 0) g_gstart[GG] = NN;
}

__global__ void __launch_bounds__(SCAN_B) k_scan_block() {
    __shared__ int sh[SCAN_B];
    int i = blockIdx.x * SCAN_B + threadIdx.x;
    int v = (i < NN) ? g_indeg[i] : 0;
    sh[threadIdx.x] = v;
    __syncthreads();
    for (int off = SCAN_B / 2; off > 0; off >>= 1) {
        if (threadIdx.x < off) sh[threadIdx.x] += sh[threadIdx.x + off];
        __syncthreads();
    }
    if (threadIdx.x == 0) g_bsum[blockIdx.x] = sh[0];
}

// Fused: per-block offset (reduce bsum[0..bid)) + in-block exclusive scan
// + row_off/cursor/dinv writes.
__global__ void __launch_bounds__(SCAN_B) k_scan_fill() {
    __shared__ int red[SCAN_B];
    __shared__ int sh[SCAN_B];
    const int bid = blockIdx.x;
    const int t = threadIdx.x;

    red[t] = (t < bid) ? g_bsum[t] : 0;   // bid <= 195 < 256
    __syncthreads();
    for (int off = SCAN_B / 2; off > 0; off >>= 1) {
        if (t < off) red[t] += red[t + off];
        __syncthreads();
    }
    const int boff = red[0];

    int i = bid * SCAN_B + t;
    int v = (i < NN) ? g_indeg[i] : 0;
    sh[t] = v;
    __syncthreads();
    for (int off = 1; off < SCAN_B; off <<= 1) {
        int u = (t >= off) ? sh[t - off] : 0;
        __syncthreads();
        sh[t] += u;
        __syncthreads();
    }
    if (i < NN) {
        int excl = boff + sh[t] - v;
        g_row_off[i] = excl;
        g_cursor[i] = excl;
        g_dinv[i] = rsqrtf((float)v + 1.0f);  // +1 self-loop
    }
    if (bid == 0 && t == 0) g_row_off[NN] = EE;
}

__global__ void k_fill(const int* __restrict__ src, const int* __restrict__ dst) {
    int e = blockIdx.x * blockDim.x + threadIdx.x;
    if (e < EE) {
        int p = atomicAdd(&g_cursor[dst[e]], 1);
        g_csr_src[p] = src[e];
    }
}

// ---------------------------------------------------------------------------
// GEMM: g_zws(fp16) = dinv[:,None] * (A @ W)  via packed f32x2 FFMA2.
// ---------------------------------------------------------------------------
#define GR 16
__global__ void __launch_bounds__(128) k_gemm(const float* __restrict__ A,
                                              const float* __restrict__ W) {
    __shared__ float2 xs2[GR][128];  // splatted: xs2[r][k] = {A[r][k], A[r][k]}
    const int row0 = blockIdx.x * GR;
    const int t = threadIdx.x;

    const float4* A4 = (const float4*)A;
    for (int i = t; i < GR * 32; i += 128) {
        int r = i >> 5, k4 = i & 31;
        float4 v = A4[(size_t)(row0 + r) * 32 + k4];
        xs2[r][4 * k4 + 0] = make_float2(v.x, v.x);
        xs2[r][4 * k4 + 1] = make_float2(v.y, v.y);
        xs2[r][4 * k4 + 2] = make_float2(v.z, v.z);
        xs2[r][4 * k4 + 3] = make_float2(v.w, v.w);
    }
    __syncthreads();

    const int cg = t & 31;
    const int rg = t >> 5;

    ull acc[4][2];
#pragma unroll
    for (int r = 0; r < 4; r++) { acc[r][0] = 0ULL; acc[r][1] = 0ULL; }

#pragma unroll 4
    for (int k = 0; k < 128; k++) {
        ulonglong2 wv = *(const ulonglong2*)&W[(size_t)k * 128 + 4 * cg];
#pragma unroll
        for (int r = 0; r < 4; r++) {
            ull a2 = *(const ull*)&xs2[4 * rg + r][k];
            FFMA2(acc[r][0], a2, wv.x);
            FFMA2(acc[r][1], a2, wv.y);
        }
    }

#pragma unroll
    for (int r = 0; r < 4; r++) {
        int row = row0 + 4 * rg + r;
        float di = g_dinv[row];
        float2 p0, p1;
        *(ull*)&p0 = acc[r][0];
        *(ull*)&p1 = acc[r][1];
        __half2 h0 = __floats2half2_rn(di * p0.x, di * p0.y);
        __half2 h1 = __floats2half2_rn(di * p1.x, di * p1.y);
        uint2 o;
        o.x = *(unsigned int*)&h0;
        o.y = *(unsigned int*)&h1;
        ((uint2*)g_zws)[(size_t)row * 32 + cg] = o;  // 256 B/row, coalesced
    }
}

// ---------------------------------------------------------------------------
// Gather + epilogue (no atomics): one warp per dst node, MLP-2, 128-thr blocks.
// fp16 gather stream (LDG.64/lane), fp32 accumulation; writes z only.
// ---------------------------------------------------------------------------
__device__ __forceinline__ void acc_h4(float4& a, uint2 u) {
    float2 f0 = __half22float2(*(__half2*)&u.x);
    float2 f1 = __half22float2(*(__half2*)&u.y);
    a.x += f0.x; a.y += f0.y; a.z += f1.x; a.w += f1.y;
}

__global__ void __launch_bounds__(128) k_gather(const float* __restrict__ b,
                                                const float* __restrict__ alpha,
                                                float* __restrict__ zout) {
    int d = blockIdx.x * 4 + (threadIdx.x >> 5);
    if (d >= NN) return;
    int lane = threadIdx.x & 31;

    const uint2* zz = (const uint2*)g_zws;
    int beg = g_row_off[d];
    int end = g_row_off[d + 1];

    float4 acc = make_float4(0.f, 0.f, 0.f, 0.f);
    float4 acc2 = make_float4(0.f, 0.f, 0.f, 0.f);
    acc_h4(acc, __ldg(&zz[(size_t)d * 32 + lane]));  // self-loop term

    int e = beg;
    for (; e + 1 < end; e += 2) {
        int s0 = g_csr_src[e];
        int s1 = g_csr_src[e + 1];
        uint2 v0 = __ldg(&zz[(size_t)s0 * 32 + lane]);
        uint2 v1 = __ldg(&zz[(size_t)s1 * 32 + lane]);
        acc_h4(acc, v0);
        acc_h4(acc2, v1);
    }
    if (e < end) {
        int s0 = g_csr_src[e];
        acc_h4(acc, __ldg(&zz[(size_t)s0 * 32 + lane]));
    }
    acc.x += acc2.x; acc.y += acc2.y; acc.z += acc2.z; acc.w += acc2.w;

    float di = g_dinv[d];
    float4 bb = __ldg(&((const float4*)b)[lane]);
    float4 al = __ldg(&((const float4*)alpha)[lane]);
    float4 h;
    h.x = di * acc.x + bb.x; h.x = (h.x > 0.f) ? h.x : al.x * h.x;
    h.y = di * acc.y + bb.y; h.y = (h.y > 0.f) ? h.y : al.y * h.y;
    h.z = di * acc.z + bb.z; h.z = (h.z > 0.f) ? h.z : al.z * h.z;
    h.w = di * acc.w + bb.w; h.w = (h.w > 0.f) ? h.w : al.w * h.w;

    ((float4*)zout)[(size_t)d * 32 + lane] = h;
}

// ---------------------------------------------------------------------------
// Pool: segment sum over sorted batch. Grid 2*GG: block g<GG sums z1 into
// pool[g][0:128]; block g>=GG sums z2 into pool[g-GG][128:256]. No atomics.
// ---------------------------------------------------------------------------
__global__ void __launch_bounds__(128) k_pool(const float* __restrict__ z1,
                                              const float* __restrict__ z2,
                                              float* __restrict__ pool) {
    int blk = blockIdx.x;
    int g = (blk < GG) ? blk : blk - GG;
    const float* z = (blk < GG) ? z1 : z2;
    int off = (blk < GG) ? 0 : HH;
    int c = threadIdx.x;

    int i0 = g_gstart[g];
    int i1 = g_gstart[g + 1];
    float s = 0.f, s2 = 0.f;
    int i = i0;
    for (; i + 1 < i1; i += 2) {
        s += z[(size_t)i * HH + c];
        s2 += z[(size_t)(i + 1) * HH + c];
    }
    if (i < i1) s += z[(size_t)i * HH + c];
    pool[(size_t)g * (2 * HH) + off + c] = s + s2;
}

// ---------------------------------------------------------------------------
extern "C" void kernel_launch(void* const* d_in, const int* in_sizes, int n_in,
                              void* d_out, int out_size) {
    const float* x     = (const float*)d_in[0];
    const int*   eidx  = (const int*)d_in[1];
    const int*   batch = (const int*)d_in[2];
    const float* W1    = (const float*)d_in[3];
    const float* b1    = (const float*)d_in[4];
    const float* W2    = (const float*)d_in[5];
    const float* b2    = (const float*)d_in[6];
    const float* alpha = (const float*)d_in[7];

    const int* src = eidx;       // edge_index[0]
    const int* dst = eidx + EE;  // edge_index[1]

    float* out  = (float*)d_out;
    float* pool = out + (size_t)NN * HH;

    // Setup
    k_indeg_zero<<<(NN + 255) / 256, 256>>>();
    k_deg<<<(EE + 255) / 256, 256>>>(dst);
    k_gstart<<<1, 256>>>(batch);
    k_scan_block<<<SCAN_NB, SCAN_B>>>();
    k_scan_fill<<<SCAN_NB, SCAN_B>>>();
    k_fill<<<(EE + 255) / 256, 256>>>(src, dst);

    float* z1;
    cudaGetSymbolAddress((void**)&z1, g_z1);

    // Layer 1
    k_gemm<<<NN / GR + (NN % GR ? 1 : 0), 128>>>(x, W1);
    k_gather<<<(NN + 3) / 4, 128>>>(b1, alpha, z1);

    // Layer 2
    k_gemm<<<NN / GR + (NN % GR ? 1 : 0), 128>>>(z1, W2);
    k_gather<<<(NN + 3) / 4, 128>>>(b2, alpha, out);

    // Pool (both layers, no atomics)
    k_pool<<<2 * GG, 128>>>(z1, out, pool);
}

// round 13
// speedup vs baseline: 1.5033x; 1.2053x over previous
#include <cuda_runtime.h>
#include <cuda_fp16.h>

#define NN 50000
#define EE 800000
#define DD 128
#define HH 128
#define GG 256

typedef unsigned long long ull;

// Scratch (__device__ globals — no allocs allowed). Statically zeroed at load;
// g_indeg is re-zeroed by a tail kernel each launch (replay-invariant).
__device__ int    g_indeg[NN];
__device__ float  g_dinv[NN];
__device__ int    g_row_off[NN + 1];
__device__ int    g_cursor[NN];
__device__ int    g_csr_src[EE];
__device__ __half g_zws[(size_t)NN * HH];  // fp16: dinv[i] * (z @ W)[i]
__device__ float  g_z1[(size_t)NN * HH];   // layer-1 output (fp32)
__device__ int    g_gstart[GG + 1];        // per-graph node ranges (batch sorted)

#define SCAN_B 256
#define SCAN_NB ((NN + SCAN_B - 1) / SCAN_B)  // 196
__device__ int g_bsum[SCAN_NB];

// tf32 convert + m16n8k8 mma (sm_80+; runs on sm_103a tensor pipe)
__device__ __forceinline__ unsigned cvt_tf32(float f) {
    unsigned r;
    asm("cvt.rna.tf32.f32 %0, %1;" : "=r"(r) : "f"(f));
    return r;
}
#define MMA_TF32(d, a, b)                                                      \
    asm("mma.sync.aligned.m16n8k8.row.col.f32.tf32.tf32.f32 "                  \
        "{%0,%1,%2,%3}, {%4,%5,%6,%7}, {%8,%9}, {%0,%1,%2,%3};"                \
        : "+f"(d[0]), "+f"(d[1]), "+f"(d[2]), "+f"(d[3])                       \
        : "r"(a[0]), "r"(a[1]), "r"(a[2]), "r"(a[3]), "r"(b[0]), "r"(b[1]))

// ---------------------------------------------------------------------------
// Setup
// ---------------------------------------------------------------------------
__global__ void k_deg(const int* __restrict__ dst) {
    int e = blockIdx.x * blockDim.x + threadIdx.x;
    if (e < EE) atomicAdd(&g_indeg[dst[e]], 1);
}

__global__ void k_gstart(const int* __restrict__ batch) {
    int g = threadIdx.x;  // 0..255
    int lo = 0, hi = NN;
    while (lo < hi) {
        int m = (lo + hi) >> 1;
        if (batch[m] < g) lo = m + 1; else hi = m;
    }
    g_gstart[g] = lo;
    if (g == 0) g_gstart[GG] = NN;
}

__global__ void k_dinv() {
    int i = blockIdx.x * blockDim.x + threadIdx.x;
    if (i < NN) g_dinv[i] = rsqrtf((float)g_indeg[i] + 1.0f);  // +1 self-loop
}

__global__ void __launch_bounds__(SCAN_B) k_scan_block() {
    __shared__ int sh[SCAN_B];
    int i = blockIdx.x * SCAN_B + threadIdx.x;
    int v = (i < NN) ? g_indeg[i] : 0;
    sh[threadIdx.x] = v;
    __syncthreads();
    for (int off = SCAN_B / 2; off > 0; off >>= 1) {
        if (threadIdx.x < off) sh[threadIdx.x] += sh[threadIdx.x + off];
        __syncthreads();
    }
    if (threadIdx.x == 0) g_bsum[blockIdx.x] = sh[0];
}

__global__ void __launch_bounds__(SCAN_B) k_scan_fill() {
    __shared__ int red[SCAN_B];
    __shared__ int sh[SCAN_B];
    const int bid = blockIdx.x;
    const int t = threadIdx.x;

    red[t] = (t < bid) ? g_bsum[t] : 0;   // bid <= 195 < 256
    __syncthreads();
    for (int off = SCAN_B / 2; off > 0; off >>= 1) {
        if (t < off) red[t] += red[t + off];
        __syncthreads();
    }
    const int boff = red[0];

    int i = bid * SCAN_B + t;
    int v = (i < NN) ? g_indeg[i] : 0;
    sh[t] = v;
    __syncthreads();
    for (int off = 1; off < SCAN_B; off <<= 1) {
        int u = (t >= off) ? sh[t - off] : 0;
        __syncthreads();
        sh[t] += u;
        __syncthreads();
    }
    if (i < NN) {
        int excl = boff + sh[t] - v;
        g_row_off[i] = excl;
        g_cursor[i] = excl;
    }
    if (bid == 0 && t == 0) g_row_off[NN] = EE;
}

__global__ void k_fill(const int* __restrict__ src, const int* __restrict__ dst) {
    int e = blockIdx.x * blockDim.x + threadIdx.x;
    if (e < EE) {
        int p = atomicAdd(&g_cursor[dst[e]], 1);
        g_csr_src[p] = src[e];
    }
}

// Tail: re-zero indeg so the next (graph-replayed) launch sees zeros.
__global__ void k_indeg_zero() {
    int i = blockIdx.x * blockDim.x + threadIdx.x;
    if (i < NN) g_indeg[i] = 0;
}

// ---------------------------------------------------------------------------
// GEMM (tensor core): g_zws(fp16) = dinv[:,None] * (A @ W), tf32 mma.sync.
// Block: 128 rows x 128 cols, 256 thr (8 warps). Warp: 64 rows x 32 cols =
// 4 m-tiles x 4 n-tiles of m16n8k8. A,W read via __ldg (L1-resident).
// ---------------------------------------------------------------------------
__global__ void __launch_bounds__(256) k_gemm_mma(const float* __restrict__ A,
                                                 const float* __restrict__ W) {
    const int w = threadIdx.x >> 5;
    const int lane = threadIdx.x & 31;
    const int g = lane >> 2;       // 0..7
    const int ti = lane & 3;       // 0..3
    const int r0 = blockIdx.x * 128 + (w & 1) * 64;
    const int c0 = (w >> 1) * 32;

    // Clamped row indices for 4 m-tiles x {g, g+8}
    int rowA[4][2];
#pragma unroll
    for (int mt = 0; mt < 4; mt++) {
        int ra = r0 + mt * 16 + g;
        int rb = ra + 8;
        rowA[mt][0] = (ra < NN) ? ra : NN - 1;
        rowA[mt][1] = (rb < NN) ? rb : NN - 1;
    }

    float d[4][4][4];
#pragma unroll
    for (int mt = 0; mt < 4; mt++)
#pragma unroll
        for (int nt = 0; nt < 4; nt++)
#pragma unroll
            for (int i = 0; i < 4; i++) d[mt][nt][i] = 0.0f;

#pragma unroll
    for (int ks = 0; ks < 16; ks++) {
        const int k0 = ks * 8;
        unsigned a[4][4];
#pragma unroll
        for (int mt = 0; mt < 4; mt++) {
            const float* p0 = A + (size_t)rowA[mt][0] * 128 + k0 + ti;
            const float* p1 = A + (size_t)rowA[mt][1] * 128 + k0 + ti;
            a[mt][0] = cvt_tf32(__ldg(p0));
            a[mt][1] = cvt_tf32(__ldg(p1));
            a[mt][2] = cvt_tf32(__ldg(p0 + 4));
            a[mt][3] = cvt_tf32(__ldg(p1 + 4));
        }
        unsigned bf[4][2];
#pragma unroll
        for (int nt = 0; nt < 4; nt++) {
            int col = c0 + nt * 8 + g;
            bf[nt][0] = cvt_tf32(__ldg(W + (size_t)(k0 + ti) * 128 + col));
            bf[nt][1] = cvt_tf32(__ldg(W + (size_t)(k0 + ti + 4) * 128 + col));
        }
#pragma unroll
        for (int mt = 0; mt < 4; mt++)
#pragma unroll
            for (int nt = 0; nt < 4; nt++)
                MMA_TF32(d[mt][nt], a[mt], bf[nt]);
    }

    // Epilogue: scale by dinv, convert fp16, store (cols 2ti,2ti+1 -> one u32)
    unsigned* zz = (unsigned*)g_zws;  // half-pair granularity
#pragma unroll
    for (int mt = 0; mt < 4; mt++) {
        int ra = r0 + mt * 16 + g;
        int rb = ra + 8;
        float dia = (ra < NN) ? g_dinv[ra] : 0.0f;
        float dib = (rb < NN) ? g_dinv[rb] : 0.0f;
#pragma unroll
        for (int nt = 0; nt < 4; nt++) {
            int col = c0 + nt * 8 + 2 * ti;
            if (ra < NN) {
                __half2 h = __floats2half2_rn(d[mt][nt][0] * dia, d[mt][nt][1] * dia);
                zz[(size_t)ra * 64 + (col >> 1)] = *(unsigned*)&h;
            }
            if (rb < NN) {
                __half2 h = __floats2half2_rn(d[mt][nt][2] * dib, d[mt][nt][3] * dib);
                zz[(size_t)rb * 64 + (col >> 1)] = *(unsigned*)&h;
            }
        }
    }
}

// ---------------------------------------------------------------------------
// Gather + epilogue (no atomics): one warp per dst node, MLP-2, 128-thr blocks.
// ---------------------------------------------------------------------------
__device__ __forceinline__ void acc_h4(float4& a, uint2 u) {
    float2 f0 = __half22float2(*(__half2*)&u.x);
    float2 f1 = __half22float2(*(__half2*)&u.y);
    a.x += f0.x; a.y += f0.y; a.z += f1.x; a.w += f1.y;
}

__global__ void __launch_bounds__(128) k_gather(const float* __restrict__ b,
                                                const float* __restrict__ alpha,
                                                float* __restrict__ zout) {
    int d = blockIdx.x * 4 + (threadIdx.x >> 5);
    if (d >= NN) return;
    int lane = threadIdx.x & 31;

    const uint2* zz = (const uint2*)g_zws;
    int beg = g_row_off[d];
    int end = g_row_off[d + 1];

    float4 acc = make_float4(0.f, 0.f, 0.f, 0.f);
    float4 acc2 = make_float4(0.f, 0.f, 0.f, 0.f);
    acc_h4(acc, __ldg(&zz[(size_t)d * 32 + lane]));  // self-loop term

    int e = beg;
    for (; e + 1 < end; e += 2) {
        int s0 = g_csr_src[e];
        int s1 = g_csr_src[e + 1];
        uint2 v0 = __ldg(&zz[(size_t)s0 * 32 + lane]);
        uint2 v1 = __ldg(&zz[(size_t)s1 * 32 + lane]);
        acc_h4(acc, v0);
        acc_h4(acc2, v1);
    }
    if (e < end) {
        int s0 = g_csr_src[e];
        acc_h4(acc, __ldg(&zz[(size_t)s0 * 32 + lane]));
    }
    acc.x += acc2.x; acc.y += acc2.y; acc.z += acc2.z; acc.w += acc2.w;

    float di = g_dinv[d];
    float4 bb = __ldg(&((const float4*)b)[lane]);
    float4 al = __ldg(&((const float4*)alpha)[lane]);
    float4 h;
    h.x = di * acc.x + bb.x; h.x = (h.x > 0.f) ? h.x : al.x * h.x;
    h.y = di * acc.y + bb.y; h.y = (h.y > 0.f) ? h.y : al.y * h.y;
    h.z = di * acc.z + bb.z; h.z = (h.z > 0.f) ? h.z : al.z * h.z;
    h.w = di * acc.w + bb.w; h.w = (h.w > 0.f) ? h.w : al.w * h.w;

    ((float4*)zout)[(size_t)d * 32 + lane] = h;
}

// ---------------------------------------------------------------------------
// Pool: segment sums over sorted batch (no atomics).
// ---------------------------------------------------------------------------
__global__ void __launch_bounds__(128) k_pool(const float* __restrict__ z1,
                                              const float* __restrict__ z2,
                                              float* __restrict__ pool) {
    int blk = blockIdx.x;
    int g = (blk < GG) ? blk : blk - GG;
    const float* z = (blk < GG) ? z1 : z2;
    int off = (blk < GG) ? 0 : HH;
    int c = threadIdx.x;

    int i0 = g_gstart[g];
    int i1 = g_gstart[g + 1];
    float s = 0.f, s2 = 0.f;
    int i = i0;
    for (; i + 1 < i1; i += 2) {
        s += z[(size_t)i * HH + c];
        s2 += z[(size_t)(i + 1) * HH + c];
    }
    if (i < i1) s += z[(size_t)i * HH + c];
    pool[(size_t)g * (2 * HH) + off + c] = s + s2;
}

// ---------------------------------------------------------------------------
extern "C" void kernel_launch(void* const* d_in, const int* in_sizes, int n_in,
                              void* d_out, int out_size) {
    const float* x     = (const float*)d_in[0];
    const int*   eidx  = (const int*)d_in[1];
    const int*   batch = (const int*)d_in[2];
    const float* W1    = (const float*)d_in[3];
    const float* b1    = (const float*)d_in[4];
    const float* W2    = (const float*)d_in[5];
    const float* b2    = (const float*)d_in[6];
    const float* alpha = (const float*)d_in[7];

    const int* src = eidx;       // edge_index[0]
    const int* dst = eidx + EE;  // edge_index[1]

    float* out  = (float*)d_out;
    float* pool = out + (size_t)NN * HH;

    float* z1;
    cudaGetSymbolAddress((void**)&z1, g_z1);

    const int GEMM_GRID = (NN + 127) / 128;  // 391

    // g_indeg is zero on entry (static init / tail kernel of previous call)
    k_deg<<<(EE + 255) / 256, 256>>>(dst);                    // 0
    k_gstart<<<1, 256>>>(batch);                              // 1
    k_dinv<<<(NN + 255) / 256, 256>>>();                      // 2
    k_gemm_mma<<<GEMM_GRID, 256>>>(x, W1);                    // 3  <- ncu probe
    k_scan_block<<<SCAN_NB, SCAN_B>>>();                      // 4
    k_scan_fill<<<SCAN_NB, SCAN_B>>>();                       // 5
    k_fill<<<(EE + 255) / 256, 256>>>(src, dst);              // 6
    k_gather<<<(NN + 3) / 4, 128>>>(b1, alpha, z1);           // 7
    k_gemm_mma<<<GEMM_GRID, 256>>>(z1, W2);                   // 8
    k_gather<<<(NN + 3) / 4, 128>>>(b2, alpha, out);          // 9
    k_pool<<<2 * GG, 128>>>(z1, out, pool);                   // 10
    k_indeg_zero<<<(NN + 255) / 256, 256>>>();                // 11 (tail reset)
}

// round 14
// speedup vs baseline: 1.9974x; 1.3287x over previous
#include <cuda_runtime.h>
#include <cuda_fp16.h>

#define NN 50000
#define EE 800000
#define DD 128
#define HH 128
#define GG 256

typedef unsigned long long ull;

// Scratch (__device__ globals — no allocs allowed). Statically zeroed at load;
// g_indeg is re-zeroed by a tail kernel each launch (replay-invariant).
__device__ int    g_indeg[NN];
__device__ float  g_dinv[NN];
__device__ int    g_row_off[NN + 1];
__device__ int    g_cursor[NN];
__device__ int    g_csr_src[EE];
__device__ __half g_zws[(size_t)NN * HH];  // fp16: dinv[i] * (z @ W)[i]
__device__ float  g_z1[(size_t)NN * HH];   // layer-1 output (fp32)
__device__ int    g_gstart[GG + 1];        // per-graph node ranges (batch sorted)

#define SCAN_B 256
#define SCAN_NB ((NN + SCAN_B - 1) / SCAN_B)  // 196
__device__ int g_bsum[SCAN_NB];

// ---------------------------------------------------------------------------
// PTX helpers
// ---------------------------------------------------------------------------
__device__ __forceinline__ unsigned smem_u32(const void* p) {
    unsigned r;
    asm("{ .reg .u64 t; cvta.to.shared.u64 t, %1; cvt.u32.u64 %0, t; }"
        : "=r"(r) : "l"(p));
    return r;
}
#define LDSM_X4(r, addr)                                                       \
    asm volatile("ldmatrix.sync.aligned.m8n8.x4.shared.b16 {%0,%1,%2,%3}, [%4];" \
                 : "=r"(r[0]), "=r"(r[1]), "=r"(r[2]), "=r"(r[3]) : "r"(addr))
#define LDSM_X4_T(r, addr)                                                     \
    asm volatile("ldmatrix.sync.aligned.m8n8.x4.trans.shared.b16 {%0,%1,%2,%3}, [%4];" \
                 : "=r"(r[0]), "=r"(r[1]), "=r"(r[2]), "=r"(r[3]) : "r"(addr))
#define MMA_F16(d, a, b0, b1)                                                  \
    asm volatile("mma.sync.aligned.m16n8k16.row.col.f32.f16.f16.f32 "          \
                 "{%0,%1,%2,%3},{%4,%5,%6,%7},{%8,%9},{%0,%1,%2,%3};"          \
                 : "+f"(d[0]), "+f"(d[1]), "+f"(d[2]), "+f"(d[3])              \
                 : "r"(a[0]), "r"(a[1]), "r"(a[2]), "r"(a[3]), "r"(b0), "r"(b1))

// ---------------------------------------------------------------------------
// Setup
// ---------------------------------------------------------------------------
__global__ void k_deg(const int* __restrict__ dst) {
    int e = blockIdx.x * blockDim.x + threadIdx.x;
    if (e < EE) atomicAdd(&g_indeg[dst[e]], 1);
}

__global__ void k_gstart(const int* __restrict__ batch) {
    int g = threadIdx.x;  // 0..255
    int lo = 0, hi = NN;
    while (lo < hi) {
        int m = (lo + hi) >> 1;
        if (batch[m] < g) lo = m + 1; else hi = m;
    }
    g_gstart[g] = lo;
    if (g == 0) g_gstart[GG] = NN;
}

__global__ void k_dinv() {
    int i = blockIdx.x * blockDim.x + threadIdx.x;
    if (i < NN) g_dinv[i] = rsqrtf((float)g_indeg[i] + 1.0f);  // +1 self-loop
}

__global__ void __launch_bounds__(SCAN_B) k_scan_block() {
    __shared__ int sh[SCAN_B];
    int i = blockIdx.x * SCAN_B + threadIdx.x;
    int v = (i < NN) ? g_indeg[i] : 0;
    sh[threadIdx.x] = v;
    __syncthreads();
    for (int off = SCAN_B / 2; off > 0; off >>= 1) {
        if (threadIdx.x < off) sh[threadIdx.x] += sh[threadIdx.x + off];
        __syncthreads();
    }
    if (threadIdx.x == 0) g_bsum[blockIdx.x] = sh[0];
}

__global__ void __launch_bounds__(SCAN_B) k_scan_fill() {
    __shared__ int red[SCAN_B];
    __shared__ int sh[SCAN_B];
    const int bid = blockIdx.x;
    const int t = threadIdx.x;

    red[t] = (t < bid) ? g_bsum[t] : 0;   // bid <= 195 < 256
    __syncthreads();
    for (int off = SCAN_B / 2; off > 0; off >>= 1) {
        if (t < off) red[t] += red[t + off];
        __syncthreads();
    }
    const int boff = red[0];

    int i = bid * SCAN_B + t;
    int v = (i < NN) ? g_indeg[i] : 0;
    sh[t] = v;
    __syncthreads();
    for (int off = 1; off < SCAN_B; off <<= 1) {
        int u = (t >= off) ? sh[t - off] : 0;
        __syncthreads();
        sh[t] += u;
        __syncthreads();
    }
    if (i < NN) {
        int excl = boff + sh[t] - v;
        g_row_off[i] = excl;
        g_cursor[i] = excl;
    }
    if (bid == 0 && t == 0) g_row_off[NN] = EE;
}

__global__ void k_fill(const int* __restrict__ src, const int* __restrict__ dst) {
    int e = blockIdx.x * blockDim.x + threadIdx.x;
    if (e < EE) {
        int p = atomicAdd(&g_cursor[dst[e]], 1);
        g_csr_src[p] = src[e];
    }
}

__global__ void k_indeg_zero() {
    int i = blockIdx.x * blockDim.x + threadIdx.x;
    if (i < NN) g_indeg[i] = 0;
}

// ---------------------------------------------------------------------------
// GEMM (fp16 HMMA + ldmatrix): g_zws(fp16) = dinv[:,None] * (A @ W).
// Block: 64 rows x 128 cols, 256 thr. A-slice + full W staged to swizzled
// fp16 smem (converted in-flight). Warp: 16 rows x 64 cols = 8 m16n8k16.
// Swizzle: 16B chunk index ^= (row & 7)  -> conflict-free LDSM.
// ---------------------------------------------------------------------------
#define GEMM_M 64
__global__ void __launch_bounds__(256) k_gemm_hmma(const float* __restrict__ A,
                                                   const float* __restrict__ W) {
    __shared__ __half a_sm[GEMM_M * 128];  // 16 KB, pitch 128 halves
    __shared__ __half w_sm[128 * 128];     // 32 KB, pitch 128 halves

    const int t = threadIdx.x;
    const int row0 = blockIdx.x * GEMM_M;

    // Stage A: 1024 16B-chunks (8 halves each); thread t -> chunks t+256j.
#pragma unroll
    for (int j = 0; j < 4; j++) {
        int ci = t + 256 * j;
        int r = ci >> 4, c8 = ci & 15;
        int gr = row0 + r; if (gr >= NN) gr = NN - 1;
        const float4* p = (const float4*)(A + (size_t)gr * 128 + c8 * 8);
        float4 v0 = __ldg(p);
        float4 v1 = __ldg(p + 1);
        __half2 h0 = __floats2half2_rn(v0.x, v0.y);
        __half2 h1 = __floats2half2_rn(v0.z, v0.w);
        __half2 h2 = __floats2half2_rn(v1.x, v1.y);
        __half2 h3 = __floats2half2_rn(v1.z, v1.w);
        uint4 u;
        u.x = *(unsigned*)&h0; u.y = *(unsigned*)&h1;
        u.z = *(unsigned*)&h2; u.w = *(unsigned*)&h3;
        *(uint4*)&a_sm[r * 128 + (c8 ^ (r & 7)) * 8] = u;
    }
    // Stage W: 2048 chunks; thread t -> chunks t+256j, j=0..7.
#pragma unroll
    for (int j = 0; j < 8; j++) {
        int ci = t + 256 * j;
        int r = ci >> 4, c8 = ci & 15;
        const float4* p = (const float4*)(W + (size_t)r * 128 + c8 * 8);
        float4 v0 = __ldg(p);
        float4 v1 = __ldg(p + 1);
        __half2 h0 = __floats2half2_rn(v0.x, v0.y);
        __half2 h1 = __floats2half2_rn(v0.z, v0.w);
        __half2 h2 = __floats2half2_rn(v1.x, v1.y);
        __half2 h3 = __floats2half2_rn(v1.z, v1.w);
        uint4 u;
        u.x = *(unsigned*)&h0; u.y = *(unsigned*)&h1;
        u.z = *(unsigned*)&h2; u.w = *(unsigned*)&h3;
        *(uint4*)&w_sm[r * 128 + (c8 ^ (r & 7)) * 8] = u;
    }
    __syncthreads();

    const int w = t >> 5, lane = t & 31;
    const int wm = (w & 3) * 16;   // warp rows: wm..wm+15
    const int wn = (w >> 2) * 64;  // warp cols: wn..wn+63
    const int q = lane >> 3;       // ldmatrix address group 0..3
    const int lr = lane & 7;

    float acc[8][4];
#pragma unroll
    for (int nt = 0; nt < 8; nt++)
#pragma unroll
        for (int i = 0; i < 4; i++) acc[nt][i] = 0.0f;

#pragma unroll
    for (int ks = 0; ks < 8; ks++) {
        const int k0 = ks * 16;
        // A fragment: m0..m3 = (rows wm+0..7 / +8..15) x (k chunk, chunk+1)
        unsigned a[4];
        {
            int r = wm + lr + ((q & 1) << 3);
            int c8 = (k0 >> 3) + (q >> 1);
            LDSM_X4(a, smem_u32(&a_sm[r * 128 + (c8 ^ (r & 7)) * 8]));
        }
        // B fragments: 4 x4.trans, each covers n16 (two n8 tiles)
        unsigned b[4][4];
#pragma unroll
        for (int p = 0; p < 4; p++) {
            int r = k0 + lr + ((q & 1) << 3);
            int c8 = ((wn + p * 16) >> 3) + (q >> 1);
            LDSM_X4_T(b[p], smem_u32(&w_sm[r * 128 + (c8 ^ (r & 7)) * 8]));
        }
#pragma unroll
        for (int p = 0; p < 4; p++) {
            MMA_F16(acc[2 * p],     a, b[p][0], b[p][1]);
            MMA_F16(acc[2 * p + 1], a, b[p][2], b[p][3]);
        }
    }

    // Epilogue: scale by dinv, convert fp16, store pairs.
    const int g = lane >> 2, ti = lane & 3;
    int ra = row0 + wm + g;
    int rb = ra + 8;
    float dia = (ra < NN) ? g_dinv[ra] : 0.0f;
    float dib = (rb < NN) ? g_dinv[rb] : 0.0f;
    unsigned* zz = (unsigned*)g_zws;  // half2 granularity, pitch 64
#pragma unroll
    for (int nt = 0; nt < 8; nt++) {
        int colh = (wn + nt * 8) >> 1;  // half2 index base
        if (ra < NN) {
            __half2 h = __floats2half2_rn(acc[nt][0] * dia, acc[nt][1] * dia);
            zz[(size_t)ra * 64 + colh + ti] = *(unsigned*)&h;
        }
        if (rb < NN) {
            __half2 h = __floats2half2_rn(acc[nt][2] * dib, acc[nt][3] * dib);
            zz[(size_t)rb * 64 + colh + ti] = *(unsigned*)&h;
        }
    }
}

// ---------------------------------------------------------------------------
// Gather + epilogue (no atomics): one warp per dst node, MLP-2, 128-thr blocks.
// ---------------------------------------------------------------------------
__device__ __forceinline__ void acc_h4(float4& a, uint2 u) {
    float2 f0 = __half22float2(*(__half2*)&u.x);
    float2 f1 = __half22float2(*(__half2*)&u.y);
    a.x += f0.x; a.y += f0.y; a.z += f1.x; a.w += f1.y;
}

__global__ void __launch_bounds__(128) k_gather(const float* __restrict__ b,
                                                const float* __restrict__ alpha,
                                                float* __restrict__ zout) {
    int d = blockIdx.x * 4 + (threadIdx.x >> 5);
    if (d >= NN) return;
    int lane = threadIdx.x & 31;

    const uint2* zz = (const uint2*)g_zws;
    int beg = g_row_off[d];
    int end = g_row_off[d + 1];

    float4 acc = make_float4(0.f, 0.f, 0.f, 0.f);
    float4 acc2 = make_float4(0.f, 0.f, 0.f, 0.f);
    acc_h4(acc, __ldg(&zz[(size_t)d * 32 + lane]));  // self-loop term

    int e = beg;
    for (; e + 1 < end; e += 2) {
        int s0 = g_csr_src[e];
        int s1 = g_csr_src[e + 1];
        uint2 v0 = __ldg(&zz[(size_t)s0 * 32 + lane]);
        uint2 v1 = __ldg(&zz[(size_t)s1 * 32 + lane]);
        acc_h4(acc, v0);
        acc_h4(acc2, v1);
    }
    if (e < end) {
        int s0 = g_csr_src[e];
        acc_h4(acc, __ldg(&zz[(size_t)s0 * 32 + lane]));
    }
    acc.x += acc2.x; acc.y += acc2.y; acc.z += acc2.z; acc.w += acc2.w;

    float di = g_dinv[d];
    float4 bb = __ldg(&((const float4*)b)[lane]);
    float4 al = __ldg(&((const float4*)alpha)[lane]);
    float4 h;
    h.x = di * acc.x + bb.x; h.x = (h.x > 0.f) ? h.x : al.x * h.x;
    h.y = di * acc.y + bb.y; h.y = (h.y > 0.f) ? h.y : al.y * h.y;
    h.z = di * acc.z + bb.z; h.z = (h.z > 0.f) ? h.z : al.z * h.z;
    h.w = di * acc.w + bb.w; h.w = (h.w > 0.f) ? h.w : al.w * h.w;

    ((float4*)zout)[(size_t)d * 32 + lane] = h;
}

// ---------------------------------------------------------------------------
// Pool: segment sums over sorted batch (no atomics).
// ---------------------------------------------------------------------------
__global__ void __launch_bounds__(128) k_pool(const float* __restrict__ z1,
                                              const float* __restrict__ z2,
                                              float* __restrict__ pool) {
    int blk = blockIdx.x;
    int g = (blk < GG) ? blk : blk - GG;
    const float* z = (blk < GG) ? z1 : z2;
    int off = (blk < GG) ? 0 : HH;
    int c = threadIdx.x;

    int i0 = g_gstart[g];
    int i1 = g_gstart[g + 1];
    float s = 0.f, s2 = 0.f;
    int i = i0;
    for (; i + 1 < i1; i += 2) {
        s += z[(size_t)i * HH + c];
        s2 += z[(size_t)(i + 1) * HH + c];
    }
    if (i < i1) s += z[(size_t)i * HH + c];
    pool[(size_t)g * (2 * HH) + off + c] = s + s2;
}

// ---------------------------------------------------------------------------
extern "C" void kernel_launch(void* const* d_in, const int* in_sizes, int n_in,
                              void* d_out, int out_size) {
    const float* x     = (const float*)d_in[0];
    const int*   eidx  = (const int*)d_in[1];
    const int*   batch = (const int*)d_in[2];
    const float* W1    = (const float*)d_in[3];
    const float* b1    = (const float*)d_in[4];
    const float* W2    = (const float*)d_in[5];
    const float* b2    = (const float*)d_in[6];
    const float* alpha = (const float*)d_in[7];

    const int* src = eidx;       // edge_index[0]
    const int* dst = eidx + EE;  // edge_index[1]

    float* out  = (float*)d_out;
    float* pool = out + (size_t)NN * HH;

    float* z1;
    cudaGetSymbolAddress((void**)&z1, g_z1);

    const int GEMM_GRID = (NN + GEMM_M - 1) / GEMM_M;  // 782

    // g_indeg is zero on entry (static init / tail kernel of previous call)
    k_deg<<<(EE + 255) / 256, 256>>>(dst);                    // 0
    k_gstart<<<1, 256>>>(batch);                              // 1
    k_dinv<<<(NN + 255) / 256, 256>>>();                      // 2
    k_gemm_hmma<<<GEMM_GRID, 256>>>(x, W1);                   // 3  <- ncu probe
    k_scan_block<<<SCAN_NB, SCAN_B>>>();                      // 4
    k_scan_fill<<<SCAN_NB, SCAN_B>>>();                       // 5
    k_fill<<<(EE + 255) / 256, 256>>>(src, dst);              // 6
    k_gather<<<(NN + 3) / 4, 128>>>(b1, alpha, z1);           // 7
    k_gemm_hmma<<<GEMM_GRID, 256>>>(z1, W2);                  // 8
    k_gather<<<(NN + 3) / 4, 128>>>(b2, alpha, out);          // 9
    k_pool<<<2 * GG, 128>>>(z1, out, pool);                   // 10
    k_indeg_zero<<<(NN + 255) / 256, 256>>>();                // 11 (tail reset)
}

// round 15
// speedup vs baseline: 2.1237x; 1.0632x over previous
#include <cuda_runtime.h>
#include <cuda_fp16.h>

#define NN 50000
#define EE 800000
#define DD 128
#define HH 128
#define GG 256

typedef unsigned long long ull;

// Scratch (__device__ globals — no allocs allowed). Statically zeroed at load;
// g_indeg is re-zeroed inside k_scan_fill each launch (replay-invariant).
__device__ int    g_indeg[NN];
__device__ float  g_dinv[NN];
__device__ int    g_row_off[NN + 1];
__device__ int    g_cursor[NN];
__device__ int    g_csr_src[EE];
__device__ __half g_zws[(size_t)NN * HH];  // fp16: dinv[i] * (z @ W)[i]
__device__ float  g_z1[(size_t)NN * HH];   // layer-1 output (fp32)
__device__ int    g_gstart[GG + 1];        // per-graph node ranges (batch sorted)

#define SCAN_B 256
#define SCAN_NB ((NN + SCAN_B - 1) / SCAN_B)  // 196
__device__ int g_bsum[SCAN_NB];

// ---------------------------------------------------------------------------
// PTX helpers
// ---------------------------------------------------------------------------
__device__ __forceinline__ unsigned smem_u32(const void* p) {
    unsigned r;
    asm("{ .reg .u64 t; cvta.to.shared.u64 t, %1; cvt.u32.u64 %0, t; }"
        : "=r"(r) : "l"(p));
    return r;
}
#define LDSM_X4(r, addr)                                                       \
    asm volatile("ldmatrix.sync.aligned.m8n8.x4.shared.b16 {%0,%1,%2,%3}, [%4];" \
                 : "=r"(r[0]), "=r"(r[1]), "=r"(r[2]), "=r"(r[3]) : "r"(addr))
#define LDSM_X4_T(r, addr)                                                     \
    asm volatile("ldmatrix.sync.aligned.m8n8.x4.trans.shared.b16 {%0,%1,%2,%3}, [%4];" \
                 : "=r"(r[0]), "=r"(r[1]), "=r"(r[2]), "=r"(r[3]) : "r"(addr))
#define MMA_F16(d, a, b0, b1)                                                  \
    asm volatile("mma.sync.aligned.m16n8k16.row.col.f32.f16.f16.f32 "          \
                 "{%0,%1,%2,%3},{%4,%5,%6,%7},{%8,%9},{%0,%1,%2,%3};"          \
                 : "+f"(d[0]), "+f"(d[1]), "+f"(d[2]), "+f"(d[3])              \
                 : "r"(a[0]), "r"(a[1]), "r"(a[2]), "r"(a[3]), "r"(b0), "r"(b1))

// ---------------------------------------------------------------------------
// Setup
// ---------------------------------------------------------------------------
__global__ void k_deg(const int* __restrict__ dst) {
    int e = blockIdx.x * blockDim.x + threadIdx.x;
    if (e < EE) atomicAdd(&g_indeg[dst[e]], 1);
}

__global__ void k_gstart(const int* __restrict__ batch) {
    int g = threadIdx.x;  // 0..255
    int lo = 0, hi = NN;
    while (lo < hi) {
        int m = (lo + hi) >> 1;
        if (batch[m] < g) lo = m + 1; else hi = m;
    }
    g_gstart[g] = lo;
    if (g == 0) g_gstart[GG] = NN;
}

__global__ void k_dinv() {
    int i = blockIdx.x * blockDim.x + threadIdx.x;
    if (i < NN) g_dinv[i] = rsqrtf((float)g_indeg[i] + 1.0f);  // +1 self-loop
}

__global__ void __launch_bounds__(SCAN_B) k_scan_block() {
    __shared__ int sh[SCAN_B];
    int i = blockIdx.x * SCAN_B + threadIdx.x;
    int v = (i < NN) ? g_indeg[i] : 0;
    sh[threadIdx.x] = v;
    __syncthreads();
    for (int off = SCAN_B / 2; off > 0; off >>= 1) {
        if (threadIdx.x < off) sh[threadIdx.x] += sh[threadIdx.x + off];
        __syncthreads();
    }
    if (threadIdx.x == 0) g_bsum[blockIdx.x] = sh[0];
}

// Fused: block offset + in-block scan + row_off/cursor writes + indeg reset
// (this is the last reader of g_indeg; zeroing here keeps replays correct).
__global__ void __launch_bounds__(SCAN_B) k_scan_fill() {
    __shared__ int red[SCAN_B];
    __shared__ int sh[SCAN_B];
    const int bid = blockIdx.x;
    const int t = threadIdx.x;

    red[t] = (t < bid) ? g_bsum[t] : 0;   // bid <= 195 < 256
    __syncthreads();
    for (int off = SCAN_B / 2; off > 0; off >>= 1) {
        if (t < off) red[t] += red[t + off];
        __syncthreads();
    }
    const int boff = red[0];

    int i = bid * SCAN_B + t;
    int v = (i < NN) ? g_indeg[i] : 0;
    sh[t] = v;
    __syncthreads();
    for (int off = 1; off < SCAN_B; off <<= 1) {
        int u = (t >= off) ? sh[t - off] : 0;
        __syncthreads();
        sh[t] += u;
        __syncthreads();
    }
    if (i < NN) {
        int excl = boff + sh[t] - v;
        g_row_off[i] = excl;
        g_cursor[i] = excl;
        g_indeg[i] = 0;  // reset for next replay
    }
    if (bid == 0 && t == 0) g_row_off[NN] = EE;
}

__global__ void k_fill(const int* __restrict__ src, const int* __restrict__ dst) {
    int e = blockIdx.x * blockDim.x + threadIdx.x;
    if (e < EE) {
        int p = atomicAdd(&g_cursor[dst[e]], 1);
        g_csr_src[p] = src[e];
    }
}

// ---------------------------------------------------------------------------
// GEMM (fp16 HMMA + ldmatrix): g_zws(fp16) = dinv[:,None] * (A @ W).
// Block: 128 rows x 128 cols, 256 thr, 64 KB smem. Warp: 32 rows x 64 cols.
// Swizzle: 16B chunk index ^= (row & 7)  -> conflict-free LDSM.
// ---------------------------------------------------------------------------
#define GEMM_M 128
__global__ void __launch_bounds__(256) k_gemm_hmma(const float* __restrict__ A,
                                                   const float* __restrict__ W) {
    __shared__ __half a_sm[GEMM_M * 128];  // 32 KB
    __shared__ __half w_sm[128 * 128];     // 32 KB

    const int t = threadIdx.x;
    const int row0 = blockIdx.x * GEMM_M;

    // Stage A: 2048 16B-chunks (8 halves each); thread t -> chunks t+256j.
#pragma unroll
    for (int j = 0; j < 8; j++) {
        int ci = t + 256 * j;
        int r = ci >> 4, c8 = ci & 15;
        int gr = row0 + r; if (gr >= NN) gr = NN - 1;
        const float4* p = (const float4*)(A + (size_t)gr * 128 + c8 * 8);
        float4 v0 = __ldg(p);
        float4 v1 = __ldg(p + 1);
        __half2 h0 = __floats2half2_rn(v0.x, v0.y);
        __half2 h1 = __floats2half2_rn(v0.z, v0.w);
        __half2 h2 = __floats2half2_rn(v1.x, v1.y);
        __half2 h3 = __floats2half2_rn(v1.z, v1.w);
        uint4 u;
        u.x = *(unsigned*)&h0; u.y = *(unsigned*)&h1;
        u.z = *(unsigned*)&h2; u.w = *(unsigned*)&h3;
        *(uint4*)&a_sm[r * 128 + (c8 ^ (r & 7)) * 8] = u;
    }
    // Stage W: 2048 chunks.
#pragma unroll
    for (int j = 0; j < 8; j++) {
        int ci = t + 256 * j;
        int r = ci >> 4, c8 = ci & 15;
        const float4* p = (const float4*)(W + (size_t)r * 128 + c8 * 8);
        float4 v0 = __ldg(p);
        float4 v1 = __ldg(p + 1);
        __half2 h0 = __floats2half2_rn(v0.x, v0.y);
        __half2 h1 = __floats2half2_rn(v0.z, v0.w);
        __half2 h2 = __floats2half2_rn(v1.x, v1.y);
        __half2 h3 = __floats2half2_rn(v1.z, v1.w);
        uint4 u;
        u.x = *(unsigned*)&h0; u.y = *(unsigned*)&h1;
        u.z = *(unsigned*)&h2; u.w = *(unsigned*)&h3;
        *(uint4*)&w_sm[r * 128 + (c8 ^ (r & 7)) * 8] = u;
    }
    __syncthreads();

    const int w = t >> 5, lane = t & 31;
    const int wm = (w & 3) * 32;   // warp rows: wm..wm+31 (2 m16 tiles)
    const int wn = (w >> 2) * 64;  // warp cols: wn..wn+63 (4 n16 tiles)
    const int q = lane >> 3;       // ldmatrix address group 0..3
    const int lr = lane & 7;

    float acc[2][8][4];
#pragma unroll
    for (int mt = 0; mt < 2; mt++)
#pragma unroll
        for (int nt = 0; nt < 8; nt++)
#pragma unroll
            for (int i = 0; i < 4; i++) acc[mt][nt][i] = 0.0f;

#pragma unroll
    for (int ks = 0; ks < 8; ks++) {
        const int k0 = ks * 16;
        unsigned a[2][4];
#pragma unroll
        for (int mt = 0; mt < 2; mt++) {
            int r = wm + mt * 16 + lr + ((q & 1) << 3);
            int c8 = (k0 >> 3) + (q >> 1);
            LDSM_X4(a[mt], smem_u32(&a_sm[r * 128 + (c8 ^ (r & 7)) * 8]));
        }
        unsigned b[4][4];
#pragma unroll
        for (int p = 0; p < 4; p++) {
            int r = k0 + lr + ((q & 1) << 3);
            int c8 = ((wn + p * 16) >> 3) + (q >> 1);
            LDSM_X4_T(b[p], smem_u32(&w_sm[r * 128 + (c8 ^ (r & 7)) * 8]));
        }
#pragma unroll
        for (int mt = 0; mt < 2; mt++)
#pragma unroll
            for (int p = 0; p < 4; p++) {
                MMA_F16(acc[mt][2 * p],     a[mt], b[p][0], b[p][1]);
                MMA_F16(acc[mt][2 * p + 1], a[mt], b[p][2], b[p][3]);
            }
    }

    // Epilogue: scale by dinv, convert fp16, store pairs.
    const int g = lane >> 2, ti = lane & 3;
    unsigned* zz = (unsigned*)g_zws;  // half2 granularity, pitch 64
#pragma unroll
    for (int mt = 0; mt < 2; mt++) {
        int ra = row0 + wm + mt * 16 + g;
        int rb = ra + 8;
        float dia = (ra < NN) ? g_dinv[ra] : 0.0f;
        float dib = (rb < NN) ? g_dinv[rb] : 0.0f;
#pragma unroll
        for (int nt = 0; nt < 8; nt++) {
            int colh = (wn + nt * 8) >> 1;
            if (ra < NN) {
                __half2 h = __floats2half2_rn(acc[mt][nt][0] * dia, acc[mt][nt][1] * dia);
                zz[(size_t)ra * 64 + colh + ti] = *(unsigned*)&h;
            }
            if (rb < NN) {
                __half2 h = __floats2half2_rn(acc[mt][nt][2] * dib, acc[mt][nt][3] * dib);
                zz[(size_t)rb * 64 + colh + ti] = *(unsigned*)&h;
            }
        }
    }
}

// ---------------------------------------------------------------------------
// Gather + epilogue (no atomics): one warp per dst node, MLP-2, 128-thr blocks.
// ---------------------------------------------------------------------------
__device__ __forceinline__ void acc_h4(float4& a, uint2 u) {
    float2 f0 = __half22float2(*(__half2*)&u.x);
    float2 f1 = __half22float2(*(__half2*)&u.y);
    a.x += f0.x; a.y += f0.y; a.z += f1.x; a.w += f1.y;
}

__global__ void __launch_bounds__(128) k_gather(const float* __restrict__ b,
                                                const float* __restrict__ alpha,
                                                float* __restrict__ zout) {
    int d = blockIdx.x * 4 + (threadIdx.x >> 5);
    if (d >= NN) return;
    int lane = threadIdx.x & 31;

    const uint2* zz = (const uint2*)g_zws;
    int beg = g_row_off[d];
    int end = g_row_off[d + 1];

    float4 acc = make_float4(0.f, 0.f, 0.f, 0.f);
    float4 acc2 = make_float4(0.f, 0.f, 0.f, 0.f);
    acc_h4(acc, __ldg(&zz[(size_t)d * 32 + lane]));  // self-loop term

    int e = beg;
    for (; e + 1 < end; e += 2) {
        int s0 = g_csr_src[e];
        int s1 = g_csr_src[e + 1];
        uint2 v0 = __ldg(&zz[(size_t)s0 * 32 + lane]);
        uint2 v1 = __ldg(&zz[(size_t)s1 * 32 + lane]);
        acc_h4(acc, v0);
        acc_h4(acc2, v1);
    }
    if (e < end) {
        int s0 = g_csr_src[e];
        acc_h4(acc, __ldg(&zz[(size_t)s0 * 32 + lane]));
    }
    acc.x += acc2.x; acc.y += acc2.y; acc.z += acc2.z; acc.w += acc2.w;

    float di = g_dinv[d];
    float4 bb = __ldg(&((const float4*)b)[lane]);
    float4 al = __ldg(&((const float4*)alpha)[lane]);
    float4 h;
    h.x = di * acc.x + bb.x; h.x = (h.x > 0.f) ? h.x : al.x * h.x;
    h.y = di * acc.y + bb.y; h.y = (h.y > 0.f) ? h.y : al.y * h.y;
    h.z = di * acc.z + bb.z; h.z = (h.z > 0.f) ? h.z : al.z * h.z;
    h.w = di * acc.w + bb.w; h.w = (h.w > 0.f) ? h.w : al.w * h.w;

    ((float4*)zout)[(size_t)d * 32 + lane] = h;
}

// ---------------------------------------------------------------------------
// Pool: segment sums over sorted batch (no atomics).
// ---------------------------------------------------------------------------
__global__ void __launch_bounds__(128) k_pool(const float* __restrict__ z1,
                                              const float* __restrict__ z2,
                                              float* __restrict__ pool) {
    int blk = blockIdx.x;
    int g = (blk < GG) ? blk : blk - GG;
    const float* z = (blk < GG) ? z1 : z2;
    int off = (blk < GG) ? 0 : HH;
    int c = threadIdx.x;

    int i0 = g_gstart[g];
    int i1 = g_gstart[g + 1];
    float s = 0.f, s2 = 0.f;
    int i = i0;
    for (; i + 1 < i1; i += 2) {
        s += z[(size_t)i * HH + c];
        s2 += z[(size_t)(i + 1) * HH + c];
    }
    if (i < i1) s += z[(size_t)i * HH + c];
    pool[(size_t)g * (2 * HH) + off + c] = s + s2;
}

// ---------------------------------------------------------------------------
extern "C" void kernel_launch(void* const* d_in, const int* in_sizes, int n_in,
                              void* d_out, int out_size) {
    const float* x     = (const float*)d_in[0];
    const int*   eidx  = (const int*)d_in[1];
    const int*   batch = (const int*)d_in[2];
    const float* W1    = (const float*)d_in[3];
    const float* b1    = (const float*)d_in[4];
    const float* W2    = (const float*)d_in[5];
    const float* b2    = (const float*)d_in[6];
    const float* alpha = (const float*)d_in[7];

    const int* src = eidx;       // edge_index[0]
    const int* dst = eidx + EE;  // edge_index[1]

    float* out  = (float*)d_out;
    float* pool = out + (size_t)NN * HH;

    float* z1;
    cudaGetSymbolAddress((void**)&z1, g_z1);

    const int GEMM_GRID = (NN + GEMM_M - 1) / GEMM_M;  // 391

    // g_indeg is zero on entry (static init / reset inside k_scan_fill)
    k_deg<<<(EE + 255) / 256, 256>>>(dst);                    // 0
    k_gstart<<<1, 256>>>(batch);                              // 1
    k_dinv<<<(NN + 255) / 256, 256>>>();                      // 2
    k_gemm_hmma<<<GEMM_GRID, 256>>>(x, W1);                   // 3  <- ncu probe
    k_scan_block<<<SCAN_NB, SCAN_B>>>();                      // 4
    k_scan_fill<<<SCAN_NB, SCAN_B>>>();                       // 5
    k_fill<<<(EE + 255) / 256, 256>>>(src, dst);              // 6
    k_gather<<<(NN + 3) / 4, 128>>>(b1, alpha, z1);           // 7
    k_gemm_hmma<<<GEMM_GRID, 256>>>(z1, W2);                  // 8
    k_gather<<<(NN + 3) / 4, 128>>>(b2, alpha, out);          // 9
    k_pool<<<2 * GG, 128>>>(z1, out, pool);                   // 10
}